// round 15
// baseline (speedup 1.0000x reference)
#include <cuda_runtime.h>
#include <cuda_bf16.h>
#include <cstdint>
#include <cstddef>

#define T_STEPS 512
#define B_BATCH 128
#define D_IN    512
#define H_DIM   512

// ---------------- device scratch (no-alloc rule) ----------------
__device__ float          g_xproj[(size_t)T_STEPS * B_BATCH * 3 * H_DIM]; // [T,B,3H]
__device__ __nv_bfloat16  g_hhi[2][(size_t)B_BATCH * H_DIM];  // [buf][row][k]
__device__ __nv_bfloat16  g_hlo[2][(size_t)B_BATCH * H_DIM];
__device__ unsigned       g_bar[T_STEPS][4];                  // [t][mi], 256 producers
// pre-converted bf16x2 planes for xproj
__device__ uint32_t       g_ahi[(size_t)T_STEPS * B_BATCH * 256];  // A hi [row][kpair]
__device__ uint32_t       g_alo[(size_t)T_STEPS * B_BATCH * 256];
__device__ uint32_t       g_whi[1536 * 256];                       // W hi, [n][kpair]
__device__ uint32_t       g_wlo[1536 * 256];

// ---------- helpers ----------
static __device__ __forceinline__ uint32_t smem_u32(const void* p) {
    uint32_t a;
    asm("{ .reg .u64 t; cvta.to.shared.u64 t, %1; cvt.u32.u64 %0, t; }"
        : "=r"(a) : "l"(p));
    return a;
}
static __device__ __forceinline__ void ldsm_x4(uint32_t& r0, uint32_t& r1,
                                               uint32_t& r2, uint32_t& r3,
                                               uint32_t addr) {
    asm volatile("ldmatrix.sync.aligned.m8n8.x4.shared.b16 {%0,%1,%2,%3}, [%4];"
                 : "=r"(r0), "=r"(r1), "=r"(r2), "=r"(r3) : "r"(addr));
}
static __device__ __forceinline__ void mma_bf16(float& c0, float& c1, float& c2, float& c3,
                                                uint32_t a0, uint32_t a1, uint32_t a2, uint32_t a3,
                                                uint32_t b0, uint32_t b1) {
    asm volatile("mma.sync.aligned.m16n8k16.row.col.f32.bf16.bf16.f32 "
                 "{%0,%1,%2,%3}, {%4,%5,%6,%7}, {%8,%9}, {%0,%1,%2,%3};"
                 : "+f"(c0), "+f"(c1), "+f"(c2), "+f"(c3)
                 : "r"(a0), "r"(a1), "r"(a2), "r"(a3), "r"(b0), "r"(b1));
}
static __device__ __forceinline__ uint32_t bf16x2_of(float lo, float hi) {
    __nv_bfloat16 a = __float2bfloat16_rn(lo);
    __nv_bfloat16 b = __float2bfloat16_rn(hi);
    return (uint32_t)__bfloat16_as_ushort(a) | ((uint32_t)__bfloat16_as_ushort(b) << 16);
}
static __device__ __forceinline__ unsigned ld_acquire(const unsigned* p) {
    unsigned v;
    asm volatile("ld.acquire.gpu.global.u32 %0, [%1];" : "=r"(v) : "l"(p) : "memory");
    return v;
}
static __device__ __forceinline__ void red_release_add1(unsigned* p) {
    asm volatile("red.release.gpu.global.add.u32 [%0], 1;" :: "l"(p) : "memory");
}
static __device__ __forceinline__ void cp_async16(uint32_t saddr, const void* gptr) {
    asm volatile("cp.async.cg.shared.global [%0], [%1], 16;"
                 :: "r"(saddr), "l"(gptr));
}
#define CP_COMMIT() asm volatile("cp.async.commit_group;" ::: "memory")
#define CP_WAIT1()  asm volatile("cp.async.wait_group 1;" ::: "memory")
#define CP_WAIT0()  asm volatile("cp.async.wait_group 0;" ::: "memory")

// ---------- prep: zero barriers; h planes from h0 ----------
__global__ void scan_prep_kernel(const float* __restrict__ h0) {
    if (blockIdx.x == 0) {
        for (int i = threadIdx.x; i < T_STEPS * 4; i += 256)
            ((unsigned*)g_bar)[i] = 0u;
    } else {
        int idx = (blockIdx.x - 1) * 256 + threadIdx.x;   // row-major [row][k]
        float v = h0[idx];
        __nv_bfloat16 hi = __float2bfloat16_rn(v);
        g_hhi[1][idx] = hi;
        g_hlo[1][idx] = __float2bfloat16_rn(v - __bfloat162float(hi));
    }
}

// ---------- conv: A [65536][512] fp32 -> hi/lo bf16x2 planes [row][256] ----------
__global__ void conv_a_kernel(const float* __restrict__ A) {
    size_t idx = (size_t)blockIdx.x * 256 + threadIdx.x;   // row*256 + kpair
    float2 v = ((const float2*)A)[idx];
    __nv_bfloat16 h0b = __float2bfloat16_rn(v.x);
    __nv_bfloat16 h1b = __float2bfloat16_rn(v.y);
    g_ahi[idx] = (uint32_t)__bfloat16_as_ushort(h0b) |
                 ((uint32_t)__bfloat16_as_ushort(h1b) << 16);
    g_alo[idx] = bf16x2_of(v.x - __bfloat162float(h0b), v.y - __bfloat162float(h1b));
}

// ---------- conv: W [512][1536] fp32 -> transposed hi/lo planes [n][256 kpair] ----------
__global__ void conv_w_kernel(const float* __restrict__ W) {
    int n = blockIdx.x;          // 0..1535
    int kp = threadIdx.x;        // 0..255
    float w0 = W[(size_t)(2 * kp) * 1536 + n];
    float w1 = W[(size_t)(2 * kp + 1) * 1536 + n];
    __nv_bfloat16 h0b = __float2bfloat16_rn(w0);
    __nv_bfloat16 h1b = __float2bfloat16_rn(w1);
    g_whi[n * 256 + kp] = (uint32_t)__bfloat16_as_ushort(h0b) |
                          ((uint32_t)__bfloat16_as_ushort(h1b) << 16);
    g_wlo[n * 256 + kp] = bf16x2_of(w0 - __bfloat162float(h0b), w1 - __bfloat162float(h1b));
}

// ---------------- x_proj GEMM: mma.sync split-bf16, cp.async 3-stage ----------
// CTA tile 128x128, 512 threads, warp grid 4(M)x4(N), warp tile m32xn32.
// ONE block sync per chunk; tail uses wait_group 0 (fixes kt=14/15 race).
#define XP_ROWSTR 40                        // bf16 per smem row (80 B)
#define XP_PLANEB (128 * XP_ROWSTR * 2)     // 10240 bytes per plane
#define XP_STAGEB (4 * XP_PLANEB)           // 40960 bytes per stage
#define XP_SMEM_BYTES (3 * XP_STAGEB)       // 122880

__global__ __launch_bounds__(512, 1) void xproj_kernel(const float* __restrict__ bi) {
    extern __shared__ __align__(16) char xsm[];
    const int tid = threadIdx.x;
    const int lane = tid & 31;
    const int wid = tid >> 5;            // 0..15
    const int warp_m = wid & 3;          // m32 group
    const int warp_n = wid >> 2;         // n32 group
    const int m0 = blockIdx.y * 128;
    const int n0 = blockIdx.x * 128;

    float acc[2][4][4];
#pragma unroll
    for (int i = 0; i < 2; ++i)
#pragma unroll
        for (int jn = 0; jn < 4; ++jn)
#pragma unroll
            for (int q = 0; q < 4; ++q) acc[i][jn][q] = 0.f;

    const int a_r = tid >> 2, a_cp = (tid & 3) * 4;
    const int w_n = tid >> 2, w_kp = (tid & 3) * 4;

    const uint32_t a_lane_off = (uint32_t)((lane & 15) * (XP_ROWSTR * 2) + (lane >> 4) * 16);
    const uint32_t b_lane_off = (uint32_t)(((lane & 7) + ((lane >> 4) << 3)) * (XP_ROWSTR * 2)
                                           + ((lane >> 3) & 1) * 16);
    const uint32_t sm_base = smem_u32(xsm);

    const uint32_t sa_off = (uint32_t)((a_r * 20 + a_cp) * 4);
    const uint32_t sw_off = (uint32_t)((w_n * 20 + w_kp) * 4);
    const size_t ga_base = (size_t)(m0 + a_r) * 256 + a_cp;
    const size_t gw_base = (size_t)(n0 + w_n) * 256 + w_kp;

    auto issue = [&](int kt) {
        const int st = kt % 3;
        const int kw = kt * 16;
        const uint32_t base = sm_base + (uint32_t)(st * XP_STAGEB);
        cp_async16(base + sa_off,                 g_ahi + ga_base + kw);
        cp_async16(base + XP_PLANEB + sa_off,     g_alo + ga_base + kw);
        cp_async16(base + 2 * XP_PLANEB + sw_off, g_whi + gw_base + kw);
        cp_async16(base + 3 * XP_PLANEB + sw_off, g_wlo + gw_base + kw);
        CP_COMMIT();
    };

    issue(0);
    issue(1);

    for (int kt = 0; kt < 16; ++kt) {
        if (kt >= 14) CP_WAIT0(); else CP_WAIT1();   // chunk kt guaranteed resident
        __syncthreads();                              // also protects stage reuse (WAR)
        if (kt + 2 < 16) issue(kt + 2);               // safe: all warps past kt-1 reads

        const uint32_t bb = sm_base + (uint32_t)((kt % 3) * XP_STAGEB);
        const uint32_t baseAH = bb;
        const uint32_t baseAL = bb + XP_PLANEB;
        const uint32_t baseWH = bb + 2 * XP_PLANEB;
        const uint32_t baseWL = bb + 3 * XP_PLANEB;
#pragma unroll
        for (int k16 = 0; k16 < 2; ++k16) {
            const uint32_t kadd = (uint32_t)(k16 * 32);
            uint32_t ah[2][4], al[2][4], bh[2][4], bl[2][4];
#pragma unroll
            for (int mt = 0; mt < 2; ++mt) {
                uint32_t ro = (uint32_t)((warp_m * 32 + mt * 16) * (XP_ROWSTR * 2));
                ldsm_x4(ah[mt][0], ah[mt][1], ah[mt][2], ah[mt][3],
                        baseAH + ro + a_lane_off + kadd);
                ldsm_x4(al[mt][0], al[mt][1], al[mt][2], al[mt][3],
                        baseAL + ro + a_lane_off + kadd);
            }
#pragma unroll
            for (int ng = 0; ng < 2; ++ng) {
                uint32_t no = (uint32_t)((warp_n * 32 + ng * 16) * (XP_ROWSTR * 2));
                ldsm_x4(bh[ng][0], bh[ng][1], bh[ng][2], bh[ng][3],
                        baseWH + no + b_lane_off + kadd);
                ldsm_x4(bl[ng][0], bl[ng][1], bl[ng][2], bl[ng][3],
                        baseWL + no + b_lane_off + kadd);
            }
#pragma unroll
            for (int mt = 0; mt < 2; ++mt)
#pragma unroll
                for (int ng = 0; ng < 2; ++ng)
#pragma unroll
                    for (int half = 0; half < 2; ++half) {
                        float* c = acc[mt][ng * 2 + half];
                        mma_bf16(c[0], c[1], c[2], c[3],
                                 ah[mt][0], ah[mt][1], ah[mt][2], ah[mt][3],
                                 bh[ng][half * 2], bh[ng][half * 2 + 1]);
                        mma_bf16(c[0], c[1], c[2], c[3],
                                 al[mt][0], al[mt][1], al[mt][2], al[mt][3],
                                 bh[ng][half * 2], bh[ng][half * 2 + 1]);
                        mma_bf16(c[0], c[1], c[2], c[3],
                                 ah[mt][0], ah[mt][1], ah[mt][2], ah[mt][3],
                                 bl[ng][half * 2], bl[ng][half * 2 + 1]);
                    }
        }
    }

#pragma unroll
    for (int nt = 0; nt < 4; ++nt) {
        int ncol = warp_n * 32 + nt * 8 + (lane & 3) * 2;
        float2 bv = *(const float2*)&bi[n0 + ncol];
#pragma unroll
        for (int mt = 0; mt < 2; ++mt) {
            int r = m0 + warp_m * 32 + mt * 16 + (lane >> 2);
            float* c = acc[mt][nt];
            float2 o0; o0.x = c[0] + bv.x; o0.y = c[1] + bv.y;
            float2 o1; o1.x = c[2] + bv.x; o1.y = c[3] + bv.y;
            *(float2*)&g_xproj[(size_t)r * 1536 + n0 + ncol] = o0;
            *(float2*)&g_xproj[(size_t)(r + 8) * 1536 + n0 + ncol] = o1;
        }
    }
}

// ---------------- persistent mma.sync GRU scan, 512 threads ----------------
// 128 CTAs: mi = bid>>5 (32 batch rows), hs = bid&31 (16 hid cols -> N=48).
// 16 warps: kc = wid>>1 (K-chunk 64), mh = wid&1 (M-half 16 rows).
// ONE block sync per step (P ordering). Flag wait is per-warp acquire spin;
// release is per-gate-warp (target 256 = 32 CTAs x 8 gate warps).
#define SC_STR  1040
#define SM_AH   0
#define SM_AL   (32 * SC_STR)
#define SM_WH   (2 * 32 * SC_STR)
#define SM_WL   (SM_WH + 48 * SC_STR)
#define SM_P    (SM_WL + 48 * SC_STR)       // 166400
#define SC_SMEM (SM_P + 8 * 32 * 50 * 4)    // 217600

__global__ __launch_bounds__(512, 1) void gru_kernel(const int* __restrict__ resets,
                                                     const float* __restrict__ h0g,
                                                     const float* __restrict__ Whrz,
                                                     const float* __restrict__ Whn,
                                                     const float* __restrict__ bhn,
                                                     float* out) {
    extern __shared__ __align__(16) char smc[];
    const uint32_t sb = smem_u32(smc);
    float* P = (float*)(smc + SM_P);
    __shared__ float bn_s[16];

    const int tid = threadIdx.x;
    const int lane = tid & 31;
    const int wid = tid >> 5;            // 0..15
    const int kc = wid >> 1;             // K-chunk 0..7 (64 k)
    const int mh = wid & 1;              // M-half 0..1 (16 rows)
    const int mi = blockIdx.x >> 5;
    const int hs = blockIdx.x & 31;
    const int j0 = hs * 16;

    float* hT = out;
    float* ys = out + (size_t)B_BATCH * H_DIM;

    if (tid < 16) bn_s[tid] = bhn[j0 + tid];

    // one-time: W slice (48 n x 512 k) hi/lo bf16
    for (int idx = tid; idx < 48 * 512; idx += 512) {
        int n = idx >> 9;
        int k = idx & 511;
        int gate = n >> 4;
        int col = j0 + (n & 15);
        float w;
        if (gate == 0)      w = Whrz[(size_t)k * 1024 + col];
        else if (gate == 1) w = Whrz[(size_t)k * 1024 + 512 + col];
        else                w = Whn[(size_t)k * 512 + col];
        __nv_bfloat16 whi = __float2bfloat16_rn(w);
        *(__nv_bfloat16*)(smc + SM_WH + n * SC_STR + k * 2) = whi;
        *(__nv_bfloat16*)(smc + SM_WL + n * SC_STR + k * 2) =
            __float2bfloat16_rn(w - __bfloat162float(whi));
    }
    __syncthreads();

    const uint32_t a_off = (uint32_t)((lane & 15) * SC_STR + (lane >> 4) * 16);
    const uint32_t b4_off = (uint32_t)(((lane & 7) + ((lane >> 4) << 3)) * SC_STR
                                       + ((lane >> 3) & 1) * 16);

    // staging role (per warp, self-contained tile)
    const int s_rowl = mh * 16 + (lane >> 1);        // 0..31
    const int s_grow = mi * 32 + s_rowl;
    const int s_k0 = kc * 64 + (lane & 1) * 32;      // 32 k per lane

    // gate role (tid < 256): 2 cols per thread
    const int gr = tid >> 3;
    const int gm = tid & 7;
    const int grow = mi * 32 + gr;
    const int j0c = j0 + 2 * gm;
    const bool gate_on = (tid < 256);

    float hp0r = 0.f, hp1r = 0.f;

    for (int t = 0; t < T_STEPS; ++t) {
        // prefetch (flag-independent)
        float2 xr2 = make_float2(0.f, 0.f), xz2 = xr2, xn2 = xr2;
        bool grst = false;
        if (gate_on) {
            const float* xb = g_xproj + ((size_t)t * B_BATCH + grow) * 1536 + j0c;
            xr2 = __ldcs((const float2*)(xb));
            xz2 = __ldcs((const float2*)(xb + 512));
            xn2 = __ldcs((const float2*)(xb + 1024));
            grst = resets[t * B_BATCH + grow] != 0;
            if (t == 0) {
                float2 hv = *(const float2*)&h0g[(size_t)grow * H_DIM + j0c];
                hp0r = hv.x; hp1r = hv.y;
            }
        }
        const bool srst = resets[t * B_BATCH + s_grow] != 0;

        // per-warp RAW wait: 256 producers of group mi at step t-1 (acquire)
        if (t > 0) {
            const unsigned* bar = &g_bar[t - 1][mi];
            unsigned v = ld_acquire(bar);
            while (v < 256u) { __nanosleep(20); v = ld_acquire(bar); }
        }

        // per-warp self-contained staging: 16 rows x 64 k hi/lo
        {
            const int pb = (t + 1) & 1;
            const size_t go = (size_t)s_grow * H_DIM + s_k0;
            const uint4* ph = (const uint4*)(g_hhi[pb] + go);
            const uint4* pl = (const uint4*)(g_hlo[pb] + go);
            char* dh = smc + SM_AH + s_rowl * SC_STR + s_k0 * 2;
            char* dl = smc + SM_AL + s_rowl * SC_STR + s_k0 * 2;
            uint4 vh[4], vl[4];
#pragma unroll
            for (int i = 0; i < 4; ++i) { vh[i] = __ldcg(ph + i); vl[i] = __ldcg(pl + i); }
            if (srst) {
#pragma unroll
                for (int i = 0; i < 4; ++i) {
                    vh[i].x = vh[i].y = vh[i].z = vh[i].w = 0u;
                    vl[i] = vh[i];
                }
            }
#pragma unroll
            for (int i = 0; i < 4; ++i) {
                *(uint4*)(dh + i * 16) = vh[i];
                *(uint4*)(dl + i * 16) = vl[i];
            }
            __syncwarp();
        }

        // MMA: M=16 x N=48 x K=64, split-bf16 (72 MMAs), own tile only
        float acc[6][4];
#pragma unroll
        for (int nt = 0; nt < 6; ++nt)
#pragma unroll
            for (int q = 0; q < 4; ++q) acc[nt][q] = 0.f;

        const uint32_t abase = sb + SM_AH + (uint32_t)(mh * 16 * SC_STR);
        const uint32_t albase = sb + SM_AL + (uint32_t)(mh * 16 * SC_STR);
        const uint32_t kbase = (uint32_t)(kc * 128);
#pragma unroll
        for (int k16 = 0; k16 < 4; ++k16) {
            const uint32_t kadd = kbase + (uint32_t)(k16 * 32);
            uint32_t ah[4], al[4], bh[3][4], bl[3][4];
            ldsm_x4(ah[0], ah[1], ah[2], ah[3], abase + a_off + kadd);
            ldsm_x4(al[0], al[1], al[2], al[3], albase + a_off + kadd);
#pragma unroll
            for (int ng = 0; ng < 3; ++ng) {
                uint32_t no = (uint32_t)(ng * 16 * SC_STR) + b4_off + kadd;
                ldsm_x4(bh[ng][0], bh[ng][1], bh[ng][2], bh[ng][3], sb + SM_WH + no);
                ldsm_x4(bl[ng][0], bl[ng][1], bl[ng][2], bl[ng][3], sb + SM_WL + no);
            }
#pragma unroll
            for (int ng = 0; ng < 3; ++ng)
#pragma unroll
                for (int half = 0; half < 2; ++half) {
                    float* c = acc[ng * 2 + half];
                    mma_bf16(c[0], c[1], c[2], c[3],
                             ah[0], ah[1], ah[2], ah[3],
                             bh[ng][half * 2], bh[ng][half * 2 + 1]);
                    mma_bf16(c[0], c[1], c[2], c[3],
                             al[0], al[1], al[2], al[3],
                             bh[ng][half * 2], bh[ng][half * 2 + 1]);
                    mma_bf16(c[0], c[1], c[2], c[3],
                             ah[0], ah[1], ah[2], ah[3],
                             bl[ng][half * 2], bl[ng][half * 2 + 1]);
                }
        }

        // warp partial into P[kc][row][50]
        {
            int r = mh * 16 + (lane >> 2);
#pragma unroll
            for (int nt = 0; nt < 6; ++nt) {
                int cc = nt * 8 + (lane & 3) * 2;
                float* c = acc[nt];
                *(float2*)&P[(kc * 32 + r) * 50 + cc] = make_float2(c[0], c[1]);
                *(float2*)&P[(kc * 32 + r + 8) * 50 + cc] = make_float2(c[2], c[3]);
            }
        }
        __syncthreads();                 // the ONE block sync: P visible to gates

        if (gate_on) {
            float dr0 = 0.f, dr1 = 0.f, dz0 = 0.f, dz1 = 0.f, dn0 = 0.f, dn1 = 0.f;
#pragma unroll
            for (int w = 0; w < 8; ++w) {
                const float* pr = P + (w * 32 + gr) * 50;
                float2 a = *(const float2*)&pr[2 * gm];
                float2 b = *(const float2*)&pr[16 + 2 * gm];
                float2 c = *(const float2*)&pr[32 + 2 * gm];
                dr0 += a.x; dr1 += a.y;
                dz0 += b.x; dz1 += b.y;
                dn0 += c.x; dn1 += c.y;
            }

            float hpx = grst ? 0.f : hp0r;
            float hpy = grst ? 0.f : hp1r;

            float rg0 = 1.f / (1.f + __expf(-(xr2.x + dr0)));
            float zg0 = 1.f / (1.f + __expf(-(xz2.x + dz0)));
            float ng0 = tanhf(xn2.x + rg0 * (dn0 + bn_s[2 * gm]));
            float h0n = (1.f - zg0) * ng0 + zg0 * hpx;

            float rg1 = 1.f / (1.f + __expf(-(xr2.y + dr1)));
            float zg1 = 1.f / (1.f + __expf(-(xz2.y + dz1)));
            float ng1 = tanhf(xn2.y + rg1 * (dn1 + bn_s[2 * gm + 1]));
            float h1n = (1.f - zg1) * ng1 + zg1 * hpy;

            hp0r = h0n; hp1r = h1n;

            // publish h planes, then per-warp release (32 lanes synced first)
            const int ob = t & 1;
            __nv_bfloat16 b0 = __float2bfloat16_rn(h0n);
            __nv_bfloat16 b1 = __float2bfloat16_rn(h1n);
            *(uint32_t*)&g_hhi[ob][(size_t)grow * H_DIM + j0c] =
                (uint32_t)__bfloat16_as_ushort(b0) | ((uint32_t)__bfloat16_as_ushort(b1) << 16);
            *(uint32_t*)&g_hlo[ob][(size_t)grow * H_DIM + j0c] =
                (uint32_t)__bfloat16_as_ushort(__float2bfloat16_rn(h0n - __bfloat162float(b0))) |
                ((uint32_t)__bfloat16_as_ushort(__float2bfloat16_rn(h1n - __bfloat162float(b1))) << 16);

            __syncwarp();
            if (lane == 0) red_release_add1(&g_bar[t][mi]);

            // ys / hT stores AFTER release (not scan state)
            float2 o; o.x = h0n; o.y = h1n;
            *(float2*)&ys[((size_t)t * B_BATCH + grow) * H_DIM + j0c] = o;
            if (t == T_STEPS - 1)
                *(float2*)&hT[(size_t)grow * H_DIM + j0c] = o;
        }
    }
}

extern "C" void kernel_launch(void* const* d_in, const int* in_sizes, int n_in,
                              void* d_out, int out_size) {
    const float* ins    = (const float*)d_in[0];   // [T,B,D]
    const int*   resets = (const int*)  d_in[1];   // [T,B]
    const float* h0     = (const float*)d_in[2];   // [B,H]
    const float* Wi     = (const float*)d_in[3];   // [D,3H]
    const float* bi     = (const float*)d_in[4];   // [3H]
    const float* Whrz   = (const float*)d_in[5];   // [H,2H]
    const float* Whn    = (const float*)d_in[6];   // [H,H]
    const float* bhn    = (const float*)d_in[7];   // [H]
    float* out = (float*)d_out;

    (void)in_sizes; (void)n_in; (void)out_size;

    cudaFuncSetAttribute(xproj_kernel,
                         cudaFuncAttributeMaxDynamicSharedMemorySize, XP_SMEM_BYTES);
    cudaFuncSetAttribute(gru_kernel,
                         cudaFuncAttributeMaxDynamicSharedMemorySize, SC_SMEM);

    scan_prep_kernel<<<257, 256>>>(h0);
    conv_a_kernel<<<65536, 256>>>(ins);
    conv_w_kernel<<<1536, 256>>>(Wi);
    {
        dim3 grid(1536 / 128, (T_STEPS * B_BATCH) / 128);
        xproj_kernel<<<grid, 512, XP_SMEM_BYTES>>>(bi);
    }
    gru_kernel<<<128, 512, SC_SMEM>>>(resets, h0, Whrz, Whn, bhn, out);
}

// round 16
// speedup vs baseline: 1.1810x; 1.1810x over previous
#include <cuda_runtime.h>
#include <cuda_bf16.h>
#include <cstdint>
#include <cstddef>

#define T_STEPS 512
#define B_BATCH 128
#define D_IN    512
#define H_DIM   512

// ---------------- device scratch (no-alloc rule) ----------------
__device__ float          g_xproj[(size_t)T_STEPS * B_BATCH * 3 * H_DIM]; // [T,B,3H]
__device__ __nv_bfloat16  g_hhi[2][(size_t)B_BATCH * H_DIM];  // [buf][row][k]
__device__ __nv_bfloat16  g_hlo[2][(size_t)B_BATCH * H_DIM];
__device__ unsigned       g_bar[T_STEPS][4];                  // [t][mi], 32 producers
// pre-converted bf16x2 planes for xproj
__device__ uint32_t       g_ahi[(size_t)T_STEPS * B_BATCH * 256];  // A hi [row][kpair]
__device__ uint32_t       g_alo[(size_t)T_STEPS * B_BATCH * 256];
__device__ uint32_t       g_whi[1536 * 256];                       // W hi, [n][kpair]
__device__ uint32_t       g_wlo[1536 * 256];

// ---------- helpers ----------
static __device__ __forceinline__ uint32_t smem_u32(const void* p) {
    uint32_t a;
    asm("{ .reg .u64 t; cvta.to.shared.u64 t, %1; cvt.u32.u64 %0, t; }"
        : "=r"(a) : "l"(p));
    return a;
}
static __device__ __forceinline__ void ldsm_x4(uint32_t& r0, uint32_t& r1,
                                               uint32_t& r2, uint32_t& r3,
                                               uint32_t addr) {
    asm volatile("ldmatrix.sync.aligned.m8n8.x4.shared.b16 {%0,%1,%2,%3}, [%4];"
                 : "=r"(r0), "=r"(r1), "=r"(r2), "=r"(r3) : "r"(addr));
}
static __device__ __forceinline__ void mma_bf16(float& c0, float& c1, float& c2, float& c3,
                                                uint32_t a0, uint32_t a1, uint32_t a2, uint32_t a3,
                                                uint32_t b0, uint32_t b1) {
    asm volatile("mma.sync.aligned.m16n8k16.row.col.f32.bf16.bf16.f32 "
                 "{%0,%1,%2,%3}, {%4,%5,%6,%7}, {%8,%9}, {%0,%1,%2,%3};"
                 : "+f"(c0), "+f"(c1), "+f"(c2), "+f"(c3)
                 : "r"(a0), "r"(a1), "r"(a2), "r"(a3), "r"(b0), "r"(b1));
}
static __device__ __forceinline__ uint32_t bf16x2_of(float lo, float hi) {
    __nv_bfloat16 a = __float2bfloat16_rn(lo);
    __nv_bfloat16 b = __float2bfloat16_rn(hi);
    return (uint32_t)__bfloat16_as_ushort(a) | ((uint32_t)__bfloat16_as_ushort(b) << 16);
}
static __device__ __forceinline__ unsigned ld_acquire(const unsigned* p) {
    unsigned v;
    asm volatile("ld.acquire.gpu.global.u32 %0, [%1];" : "=r"(v) : "l"(p) : "memory");
    return v;
}
static __device__ __forceinline__ void red_release_add1(unsigned* p) {
    asm volatile("red.release.gpu.global.add.u32 [%0], 1;" :: "l"(p) : "memory");
}
static __device__ __forceinline__ void cp_async16(uint32_t saddr, const void* gptr) {
    asm volatile("cp.async.cg.shared.global [%0], [%1], 16;"
                 :: "r"(saddr), "l"(gptr));
}
#define CP_COMMIT() asm volatile("cp.async.commit_group;" ::: "memory")
#define CP_WAIT1()  asm volatile("cp.async.wait_group 1;" ::: "memory")
#define CP_WAIT0()  asm volatile("cp.async.wait_group 0;" ::: "memory")

// ---------- prep: zero barriers; h planes from h0 ----------
__global__ void scan_prep_kernel(const float* __restrict__ h0) {
    if (blockIdx.x == 0) {
        for (int i = threadIdx.x; i < T_STEPS * 4; i += 256)
            ((unsigned*)g_bar)[i] = 0u;
    } else {
        int idx = (blockIdx.x - 1) * 256 + threadIdx.x;   // row-major [row][k]
        float v = h0[idx];
        __nv_bfloat16 hi = __float2bfloat16_rn(v);
        g_hhi[1][idx] = hi;
        g_hlo[1][idx] = __float2bfloat16_rn(v - __bfloat162float(hi));
    }
}

// ---------- conv: A [65536][512] fp32 -> hi/lo bf16x2 planes [row][256] ----------
__global__ void conv_a_kernel(const float* __restrict__ A) {
    size_t idx = (size_t)blockIdx.x * 256 + threadIdx.x;   // row*256 + kpair
    float2 v = ((const float2*)A)[idx];
    __nv_bfloat16 h0b = __float2bfloat16_rn(v.x);
    __nv_bfloat16 h1b = __float2bfloat16_rn(v.y);
    g_ahi[idx] = (uint32_t)__bfloat16_as_ushort(h0b) |
                 ((uint32_t)__bfloat16_as_ushort(h1b) << 16);
    g_alo[idx] = bf16x2_of(v.x - __bfloat162float(h0b), v.y - __bfloat162float(h1b));
}

// ---------- conv: W [512][1536] fp32 -> transposed hi/lo planes [n][256 kpair] ----------
__global__ void conv_w_kernel(const float* __restrict__ W) {
    int n = blockIdx.x;          // 0..1535
    int kp = threadIdx.x;        // 0..255
    float w0 = W[(size_t)(2 * kp) * 1536 + n];
    float w1 = W[(size_t)(2 * kp + 1) * 1536 + n];
    __nv_bfloat16 h0b = __float2bfloat16_rn(w0);
    __nv_bfloat16 h1b = __float2bfloat16_rn(w1);
    g_whi[n * 256 + kp] = (uint32_t)__bfloat16_as_ushort(h0b) |
                          ((uint32_t)__bfloat16_as_ushort(h1b) << 16);
    g_wlo[n * 256 + kp] = bf16x2_of(w0 - __bfloat162float(h0b), w1 - __bfloat162float(h1b));
}

// ---------------- x_proj GEMM: mma.sync split-bf16, cp.async 3-stage (r15) ---
// CTA tile 128x128, 512 threads, warp grid 4(M)x4(N), warp tile m32xn32.
// ONE block sync per chunk; tail uses wait_group 0.
#define XP_ROWSTR 40                        // bf16 per smem row (80 B)
#define XP_PLANEB (128 * XP_ROWSTR * 2)     // 10240 bytes per plane
#define XP_STAGEB (4 * XP_PLANEB)           // 40960 bytes per stage
#define XP_SMEM_BYTES (3 * XP_STAGEB)       // 122880

__global__ __launch_bounds__(512, 1) void xproj_kernel(const float* __restrict__ bi) {
    extern __shared__ __align__(16) char xsm[];
    const int tid = threadIdx.x;
    const int lane = tid & 31;
    const int wid = tid >> 5;            // 0..15
    const int warp_m = wid & 3;          // m32 group
    const int warp_n = wid >> 2;         // n32 group
    const int m0 = blockIdx.y * 128;
    const int n0 = blockIdx.x * 128;

    float acc[2][4][4];
#pragma unroll
    for (int i = 0; i < 2; ++i)
#pragma unroll
        for (int jn = 0; jn < 4; ++jn)
#pragma unroll
            for (int q = 0; q < 4; ++q) acc[i][jn][q] = 0.f;

    const int a_r = tid >> 2, a_cp = (tid & 3) * 4;
    const int w_n = tid >> 2, w_kp = (tid & 3) * 4;

    const uint32_t a_lane_off = (uint32_t)((lane & 15) * (XP_ROWSTR * 2) + (lane >> 4) * 16);
    const uint32_t b_lane_off = (uint32_t)(((lane & 7) + ((lane >> 4) << 3)) * (XP_ROWSTR * 2)
                                           + ((lane >> 3) & 1) * 16);
    const uint32_t sm_base = smem_u32(xsm);

    const uint32_t sa_off = (uint32_t)((a_r * 20 + a_cp) * 4);
    const uint32_t sw_off = (uint32_t)((w_n * 20 + w_kp) * 4);
    const size_t ga_base = (size_t)(m0 + a_r) * 256 + a_cp;
    const size_t gw_base = (size_t)(n0 + w_n) * 256 + w_kp;

    auto issue = [&](int kt) {
        const int st = kt % 3;
        const int kw = kt * 16;
        const uint32_t base = sm_base + (uint32_t)(st * XP_STAGEB);
        cp_async16(base + sa_off,                 g_ahi + ga_base + kw);
        cp_async16(base + XP_PLANEB + sa_off,     g_alo + ga_base + kw);
        cp_async16(base + 2 * XP_PLANEB + sw_off, g_whi + gw_base + kw);
        cp_async16(base + 3 * XP_PLANEB + sw_off, g_wlo + gw_base + kw);
        CP_COMMIT();
    };

    issue(0);
    issue(1);

    for (int kt = 0; kt < 16; ++kt) {
        if (kt >= 14) CP_WAIT0(); else CP_WAIT1();   // chunk kt resident
        __syncthreads();                              // also protects stage reuse
        if (kt + 2 < 16) issue(kt + 2);

        const uint32_t bb = sm_base + (uint32_t)((kt % 3) * XP_STAGEB);
        const uint32_t baseAH = bb;
        const uint32_t baseAL = bb + XP_PLANEB;
        const uint32_t baseWH = bb + 2 * XP_PLANEB;
        const uint32_t baseWL = bb + 3 * XP_PLANEB;
#pragma unroll
        for (int k16 = 0; k16 < 2; ++k16) {
            const uint32_t kadd = (uint32_t)(k16 * 32);
            uint32_t ah[2][4], al[2][4], bh[2][4], bl[2][4];
#pragma unroll
            for (int mt = 0; mt < 2; ++mt) {
                uint32_t ro = (uint32_t)((warp_m * 32 + mt * 16) * (XP_ROWSTR * 2));
                ldsm_x4(ah[mt][0], ah[mt][1], ah[mt][2], ah[mt][3],
                        baseAH + ro + a_lane_off + kadd);
                ldsm_x4(al[mt][0], al[mt][1], al[mt][2], al[mt][3],
                        baseAL + ro + a_lane_off + kadd);
            }
#pragma unroll
            for (int ng = 0; ng < 2; ++ng) {
                uint32_t no = (uint32_t)((warp_n * 32 + ng * 16) * (XP_ROWSTR * 2));
                ldsm_x4(bh[ng][0], bh[ng][1], bh[ng][2], bh[ng][3],
                        baseWH + no + b_lane_off + kadd);
                ldsm_x4(bl[ng][0], bl[ng][1], bl[ng][2], bl[ng][3],
                        baseWL + no + b_lane_off + kadd);
            }
#pragma unroll
            for (int mt = 0; mt < 2; ++mt)
#pragma unroll
                for (int ng = 0; ng < 2; ++ng)
#pragma unroll
                    for (int half = 0; half < 2; ++half) {
                        float* c = acc[mt][ng * 2 + half];
                        mma_bf16(c[0], c[1], c[2], c[3],
                                 ah[mt][0], ah[mt][1], ah[mt][2], ah[mt][3],
                                 bh[ng][half * 2], bh[ng][half * 2 + 1]);
                        mma_bf16(c[0], c[1], c[2], c[3],
                                 al[mt][0], al[mt][1], al[mt][2], al[mt][3],
                                 bh[ng][half * 2], bh[ng][half * 2 + 1]);
                        mma_bf16(c[0], c[1], c[2], c[3],
                                 ah[mt][0], ah[mt][1], ah[mt][2], ah[mt][3],
                                 bl[ng][half * 2], bl[ng][half * 2 + 1]);
                    }
        }
    }

#pragma unroll
    for (int nt = 0; nt < 4; ++nt) {
        int ncol = warp_n * 32 + nt * 8 + (lane & 3) * 2;
        float2 bv = *(const float2*)&bi[n0 + ncol];
#pragma unroll
        for (int mt = 0; mt < 2; ++mt) {
            int r = m0 + warp_m * 32 + mt * 16 + (lane >> 2);
            float* c = acc[mt][nt];
            float2 o0; o0.x = c[0] + bv.x; o0.y = c[1] + bv.y;
            float2 o1; o1.x = c[2] + bv.x; o1.y = c[3] + bv.y;
            *(float2*)&g_xproj[(size_t)r * 1536 + n0 + ncol] = o0;
            *(float2*)&g_xproj[(size_t)(r + 8) * 1536 + n0 + ncol] = o1;
        }
    }
}

// ---------------- persistent mma.sync GRU scan, 512 threads (r14, best) -----
// 128 CTAs: mi = bid>>5 (32 batch rows), hs = bid&31 (16 hid cols -> N=48).
// 16 warps: kc = wid>>1 (K-chunk 64), mh = wid&1 (M-half 16 rows).
// tid0 acquire spin (target 32) + 3 block syncs + tid0 block release.
#define SC_STR  1040
#define SM_AH   0
#define SM_AL   (32 * SC_STR)
#define SM_WH   (2 * 32 * SC_STR)
#define SM_WL   (SM_WH + 48 * SC_STR)
#define SM_P    (SM_WL + 48 * SC_STR)       // 166400
#define SC_SMEM (SM_P + 8 * 32 * 50 * 4)    // 217600

__global__ __launch_bounds__(512, 1) void gru_kernel(const int* __restrict__ resets,
                                                     const float* __restrict__ h0g,
                                                     const float* __restrict__ Whrz,
                                                     const float* __restrict__ Whn,
                                                     const float* __restrict__ bhn,
                                                     float* out) {
    extern __shared__ __align__(16) char smc[];
    const uint32_t sb = smem_u32(smc);
    float* P = (float*)(smc + SM_P);
    __shared__ float bn_s[16];

    const int tid = threadIdx.x;
    const int lane = tid & 31;
    const int wid = tid >> 5;            // 0..15
    const int kc = wid >> 1;             // K-chunk 0..7 (64 k)
    const int mh = wid & 1;              // M-half 0..1 (16 rows)
    const int mi = blockIdx.x >> 5;
    const int hs = blockIdx.x & 31;
    const int j0 = hs * 16;

    float* hT = out;
    float* ys = out + (size_t)B_BATCH * H_DIM;

    if (tid < 16) bn_s[tid] = bhn[j0 + tid];

    // one-time: W slice (48 n x 512 k) hi/lo bf16
    for (int idx = tid; idx < 48 * 512; idx += 512) {
        int n = idx >> 9;
        int k = idx & 511;
        int gate = n >> 4;
        int col = j0 + (n & 15);
        float w;
        if (gate == 0)      w = Whrz[(size_t)k * 1024 + col];
        else if (gate == 1) w = Whrz[(size_t)k * 1024 + 512 + col];
        else                w = Whn[(size_t)k * 512 + col];
        __nv_bfloat16 whi = __float2bfloat16_rn(w);
        *(__nv_bfloat16*)(smc + SM_WH + n * SC_STR + k * 2) = whi;
        *(__nv_bfloat16*)(smc + SM_WL + n * SC_STR + k * 2) =
            __float2bfloat16_rn(w - __bfloat162float(whi));
    }
    __syncthreads();

    const uint32_t a_off = (uint32_t)((lane & 15) * SC_STR + (lane >> 4) * 16);
    const uint32_t b4_off = (uint32_t)(((lane & 7) + ((lane >> 4) << 3)) * SC_STR
                                       + ((lane >> 3) & 1) * 16);

    // staging role (per warp, self-contained tile)
    const int s_rowl = mh * 16 + (lane >> 1);        // 0..31
    const int s_grow = mi * 32 + s_rowl;
    const int s_k0 = kc * 64 + (lane & 1) * 32;      // 32 k per lane

    // gate role (tid < 256): 2 cols per thread
    const int gr = tid >> 3;
    const int gm = tid & 7;
    const int grow = mi * 32 + gr;
    const int j0c = j0 + 2 * gm;
    const bool gate_on = (tid < 256);

    float hp0r = 0.f, hp1r = 0.f;

    for (int t = 0; t < T_STEPS; ++t) {
        // prefetch (flag-independent)
        float2 xr2 = make_float2(0.f, 0.f), xz2 = xr2, xn2 = xr2;
        bool grst = false;
        if (gate_on) {
            const float* xb = g_xproj + ((size_t)t * B_BATCH + grow) * 1536 + j0c;
            xr2 = __ldcs((const float2*)(xb));
            xz2 = __ldcs((const float2*)(xb + 512));
            xn2 = __ldcs((const float2*)(xb + 1024));
            grst = resets[t * B_BATCH + grow] != 0;
            if (t == 0) {
                float2 hv = *(const float2*)&h0g[(size_t)grow * H_DIM + j0c];
                hp0r = hv.x; hp1r = hv.y;
            }
        }
        const bool srst = resets[t * B_BATCH + s_grow] != 0;

        // wait: 32 producers of group mi at step t-1 (tid0 acquire spin)
        if (t > 0 && tid == 0) {
            const unsigned* bar = &g_bar[t - 1][mi];
            unsigned v = ld_acquire(bar);
            while (v < 32u) { __nanosleep(32); v = ld_acquire(bar); }
        }
        __syncthreads();                           // sync 1

        // per-warp self-contained staging: 16 rows x 64 k hi/lo
        {
            const int pb = (t + 1) & 1;
            const size_t go = (size_t)s_grow * H_DIM + s_k0;
            const uint4* ph = (const uint4*)(g_hhi[pb] + go);
            const uint4* pl = (const uint4*)(g_hlo[pb] + go);
            char* dh = smc + SM_AH + s_rowl * SC_STR + s_k0 * 2;
            char* dl = smc + SM_AL + s_rowl * SC_STR + s_k0 * 2;
            uint4 vh[4], vl[4];
#pragma unroll
            for (int i = 0; i < 4; ++i) { vh[i] = __ldcg(ph + i); vl[i] = __ldcg(pl + i); }
            if (srst) {
#pragma unroll
                for (int i = 0; i < 4; ++i) {
                    vh[i].x = vh[i].y = vh[i].z = vh[i].w = 0u;
                    vl[i] = vh[i];
                }
            }
#pragma unroll
            for (int i = 0; i < 4; ++i) {
                *(uint4*)(dh + i * 16) = vh[i];
                *(uint4*)(dl + i * 16) = vl[i];
            }
            __syncwarp();
        }

        // MMA: M=16 x N=48 x K=64, split-bf16 (72 MMAs), own tile only
        float acc[6][4];
#pragma unroll
        for (int nt = 0; nt < 6; ++nt)
#pragma unroll
            for (int q = 0; q < 4; ++q) acc[nt][q] = 0.f;

        const uint32_t abase = sb + SM_AH + (uint32_t)(mh * 16 * SC_STR);
        const uint32_t albase = sb + SM_AL + (uint32_t)(mh * 16 * SC_STR);
        const uint32_t kbase = (uint32_t)(kc * 128);
#pragma unroll
        for (int k16 = 0; k16 < 4; ++k16) {
            const uint32_t kadd = kbase + (uint32_t)(k16 * 32);
            uint32_t ah[4], al[4], bh[3][4], bl[3][4];
            ldsm_x4(ah[0], ah[1], ah[2], ah[3], abase + a_off + kadd);
            ldsm_x4(al[0], al[1], al[2], al[3], albase + a_off + kadd);
#pragma unroll
            for (int ng = 0; ng < 3; ++ng) {
                uint32_t no = (uint32_t)(ng * 16 * SC_STR) + b4_off + kadd;
                ldsm_x4(bh[ng][0], bh[ng][1], bh[ng][2], bh[ng][3], sb + SM_WH + no);
                ldsm_x4(bl[ng][0], bl[ng][1], bl[ng][2], bl[ng][3], sb + SM_WL + no);
            }
#pragma unroll
            for (int ng = 0; ng < 3; ++ng)
#pragma unroll
                for (int half = 0; half < 2; ++half) {
                    float* c = acc[ng * 2 + half];
                    mma_bf16(c[0], c[1], c[2], c[3],
                             ah[0], ah[1], ah[2], ah[3],
                             bh[ng][half * 2], bh[ng][half * 2 + 1]);
                    mma_bf16(c[0], c[1], c[2], c[3],
                             al[0], al[1], al[2], al[3],
                             bh[ng][half * 2], bh[ng][half * 2 + 1]);
                    mma_bf16(c[0], c[1], c[2], c[3],
                             ah[0], ah[1], ah[2], ah[3],
                             bl[ng][half * 2], bl[ng][half * 2 + 1]);
                }
        }

        // warp partial into P[kc][row][50]
        {
            int r = mh * 16 + (lane >> 2);
#pragma unroll
            for (int nt = 0; nt < 6; ++nt) {
                int cc = nt * 8 + (lane & 3) * 2;
                float* c = acc[nt];
                *(float2*)&P[(kc * 32 + r) * 50 + cc] = make_float2(c[0], c[1]);
                *(float2*)&P[(kc * 32 + r + 8) * 50 + cc] = make_float2(c[2], c[3]);
            }
        }
        __syncthreads();                           // sync 2

        if (gate_on) {
            float dr0 = 0.f, dr1 = 0.f, dz0 = 0.f, dz1 = 0.f, dn0 = 0.f, dn1 = 0.f;
#pragma unroll
            for (int w = 0; w < 8; ++w) {
                const float* pr = P + (w * 32 + gr) * 50;
                float2 a = *(const float2*)&pr[2 * gm];
                float2 b = *(const float2*)&pr[16 + 2 * gm];
                float2 c = *(const float2*)&pr[32 + 2 * gm];
                dr0 += a.x; dr1 += a.y;
                dz0 += b.x; dz1 += b.y;
                dn0 += c.x; dn1 += c.y;
            }

            float hpx = grst ? 0.f : hp0r;
            float hpy = grst ? 0.f : hp1r;

            float rg0 = 1.f / (1.f + __expf(-(xr2.x + dr0)));
            float zg0 = 1.f / (1.f + __expf(-(xz2.x + dz0)));
            float ng0 = tanhf(xn2.x + rg0 * (dn0 + bn_s[2 * gm]));
            float h0n = (1.f - zg0) * ng0 + zg0 * hpx;

            float rg1 = 1.f / (1.f + __expf(-(xr2.y + dr1)));
            float zg1 = 1.f / (1.f + __expf(-(xz2.y + dz1)));
            float ng1 = tanhf(xn2.y + rg1 * (dn1 + bn_s[2 * gm + 1]));
            float h1n = (1.f - zg1) * ng1 + zg1 * hpy;

            hp0r = h0n; hp1r = h1n;

            // publish h planes (scan state) FIRST
            const int ob = t & 1;
            __nv_bfloat16 b0 = __float2bfloat16_rn(h0n);
            __nv_bfloat16 b1 = __float2bfloat16_rn(h1n);
            *(uint32_t*)&g_hhi[ob][(size_t)grow * H_DIM + j0c] =
                (uint32_t)__bfloat16_as_ushort(b0) | ((uint32_t)__bfloat16_as_ushort(b1) << 16);
            *(uint32_t*)&g_hlo[ob][(size_t)grow * H_DIM + j0c] =
                (uint32_t)__bfloat16_as_ushort(__float2bfloat16_rn(h0n - __bfloat162float(b0))) |
                ((uint32_t)__bfloat16_as_ushort(__float2bfloat16_rn(h1n - __bfloat162float(b1))) << 16);
        }

        __syncthreads();                           // sync 3: plane stores issued
        if (tid == 0) red_release_add1(&g_bar[t][mi]);

        // ys / hT stores AFTER release (not scan state)
        if (gate_on) {
            float2 o; o.x = hp0r; o.y = hp1r;
            *(float2*)&ys[((size_t)t * B_BATCH + grow) * H_DIM + j0c] = o;
            if (t == T_STEPS - 1)
                *(float2*)&hT[(size_t)grow * H_DIM + j0c] = o;
        }
    }
}

extern "C" void kernel_launch(void* const* d_in, const int* in_sizes, int n_in,
                              void* d_out, int out_size) {
    const float* ins    = (const float*)d_in[0];   // [T,B,D]
    const int*   resets = (const int*)  d_in[1];   // [T,B]
    const float* h0     = (const float*)d_in[2];   // [B,H]
    const float* Wi     = (const float*)d_in[3];   // [D,3H]
    const float* bi     = (const float*)d_in[4];   // [3H]
    const float* Whrz   = (const float*)d_in[5];   // [H,2H]
    const float* Whn    = (const float*)d_in[6];   // [H,H]
    const float* bhn    = (const float*)d_in[7];   // [H]
    float* out = (float*)d_out;

    (void)in_sizes; (void)n_in; (void)out_size;

    cudaFuncSetAttribute(xproj_kernel,
                         cudaFuncAttributeMaxDynamicSharedMemorySize, XP_SMEM_BYTES);
    cudaFuncSetAttribute(gru_kernel,
                         cudaFuncAttributeMaxDynamicSharedMemorySize, SC_SMEM);

    scan_prep_kernel<<<257, 256>>>(h0);
    conv_a_kernel<<<65536, 256>>>(ins);
    conv_w_kernel<<<1536, 256>>>(Wi);
    {
        dim3 grid(1536 / 128, (T_STEPS * B_BATCH) / 128);
        xproj_kernel<<<grid, 512, XP_SMEM_BYTES>>>(bi);
    }
    gru_kernel<<<128, 512, SC_SMEM>>>(resets, h0, Whrz, Whn, bhn, out);
}